// round 10
// baseline (speedup 1.0000x reference)
#include <cuda_runtime.h>
#include <cuda_bf16.h>
#include <cstdint>
#include <math.h>

#define NP 64
#define MM 512
#define DD 256
#define MARGIN 0.2f

__device__ float  g_psum[NP];
__device__ float  g_pcnt[NP];
__device__ float  g_tsort[(size_t)NP * MM * 16];   // per-anchor sorted C values
__device__ float2 g_tsuf [(size_t)NP * MM * 17];   // per-anchor (suffix sum, count)
__device__ int    g_ready[NP * 4];                 // per (part, diag block) flag
// all zero-initialized at module load; final_kernel re-zeros after each launch

// off-diagonal tile map (6 tiles of the 4x4 upper triangle)
__constant__ int c_oby[6] = {0,0,0,1,1,2};
__constant__ int c_obx[6] = {1,2,3,2,3,3};

// ---------------------------------------------------------------------------
__device__ __forceinline__ void split2(float x0, float x1, uint32_t& hi, uint32_t& lo) {
    uint32_t h;
    asm("cvt.rn.bf16x2.f32 %0, %1, %2;" : "=r"(h) : "f"(x1), "f"(x0));
    float h0 = __uint_as_float(h << 16);
    float h1 = __uint_as_float(h & 0xFFFF0000u);
    float r0 = x0 - h0, r1 = x1 - h1;
    asm("cvt.rn.bf16x2.f32 %0, %1, %2;" : "=r"(lo) : "f"(r1), "f"(r0));
    hi = h;
}

#define MMA16816(c0,c1,c2,c3, a0,a1,a2,a3, b0,b1) \
    asm volatile("mma.sync.aligned.m16n8k16.row.col.f32.bf16.bf16.f32 " \
                 "{%0,%1,%2,%3}, {%4,%5,%6,%7}, {%8,%9}, {%0,%1,%2,%3};" \
                 : "+f"(c0), "+f"(c1), "+f"(c2), "+f"(c3) \
                 : "r"(a0), "r"(a1), "r"(a2), "r"(a3), "r"(b0), "r"(b1))

// SMEM layout. Mainloop operands [0, 40960); epilogue tables overlay after a
// barrier (all table writes happen post-mainloop). Norms/reduce live above.
#define LDA 40
#define TILE_B (128 * LDA * 2)        // 10240
#define OFF_AHI 0
#define OFF_ALO (TILE_B)
#define OFF_BHI (2 * TILE_B)
#define OFF_BLO (3 * TILE_B)          // operands end at 40960
#define OFF_SR  0                     // float [128*20]  (stride 20, f4-aligned)
#define OFF_TR  10240                 // float2[128*17] -> 27648
#define OFF_SC  27648                 // float [128*20] (diag: sPos 128*16)
#define OFF_TC  37888                 // float2[128*17] -> 55296
#define OFF_NRM 55296                 // 256 floats -> 56320
#define OFF_RED 56320                 // 16 floats
#define SMEM_TOTAL 56448

__device__ __forceinline__ void load_chunk(
    const float* __restrict__ src, int k0, char* smem, int off_hi, int off_lo,
    int tid, float* __restrict__ nacc)
{
    uint16_t* shi = reinterpret_cast<uint16_t*>(smem + off_hi);
    uint16_t* slo = reinterpret_cast<uint16_t*>(smem + off_lo);
#pragma unroll
    for (int it = 0; it < 4; it++) {
        int q   = tid + (it << 8);
        int row = q >> 3;
        int c4  = q & 7;
        float4 v = *reinterpret_cast<const float4*>(src + (size_t)row * DD + k0 + (c4 << 2));
        nacc[it] = fmaf(v.x, v.x, nacc[it]);
        nacc[it] = fmaf(v.y, v.y, nacc[it]);
        nacc[it] = fmaf(v.z, v.z, nacc[it]);
        nacc[it] = fmaf(v.w, v.w, nacc[it]);
        uint32_t h0, h1, l0, l1;
        split2(v.x, v.y, h0, l0);
        split2(v.z, v.w, h1, l1);
        int idx = row * LDA + (c4 << 2);
        *reinterpret_cast<uint2*>(&shi[idx]) = make_uint2(h0, h1);
        *reinterpret_cast<uint2*>(&slo[idx]) = make_uint2(l0, l1);
    }
}

// 2-step vectorized search: reg-compare vs S[7], 2 independent LDS.128 of the
// surviving 8 sorted values, 8-way parallel count. idx = #{C <= d} in [0,16].
__device__ __forceinline__ void searchv(
    const float* __restrict__ Sbase, const float2* __restrict__ T,
    float s7, float d, float& aA, float& aB, float& aC)
{
    const float4* S4 = reinterpret_cast<const float4*>(Sbase);
    int off = (s7 <= d) ? 2 : 0;
    float4 q0 = S4[off];
    float4 q1 = S4[off + 1];
    int idx = (off << 2)
        + (int)(q0.x <= d) + (int)(q0.y <= d) + (int)(q0.z <= d) + (int)(q0.w <= d)
        + (int)(q1.x <= d) + (int)(q1.y <= d) + (int)(q1.z <= d) + (int)(q1.w <= d);
    float2 t = T[idx];
    aA += t.x;
    aB  = fmaf(t.y, d, aB);
    aC += t.y;
}

// ---------------------------------------------------------------------------
// fused GEMM + norms + table build (diag) + hinge. 1-D grid of 640:
//   bid < 256  -> diag:    p = bid>>2, by = bx = bid&3 (flag index = bid)
//   bid >= 256 -> offdiag: q = bid-256, p = q/6, tile = q%6
// ---------------------------------------------------------------------------
__global__ void __launch_bounds__(256, 2) fused_kernel(const float* __restrict__ feat) {
    extern __shared__ char smem[];
    const int tid = threadIdx.x;
    const int w = tid >> 5, lane = tid & 31;
    const int g = lane >> 2, tg = lane & 3;
    const int wm = w >> 1, wn = w & 1;
    const int bid = blockIdx.x;
    const bool diag = (bid < 256);
    int p, by, bx;
    if (diag) {
        p = bid >> 2; by = bx = bid & 3;
    } else {
        int q = bid - 256;
        p = q / 6;
        int t = q - p * 6;
        by = c_oby[t]; bx = c_obx[t];
    }

    float* sNi = reinterpret_cast<float*>(smem + OFF_NRM);
    float* sNj = diag ? sNi : (sNi + 128);

    const float* Abase = feat + ((size_t)p * MM + (size_t)by * 128) * DD;
    const float* Bbase = feat + ((size_t)p * MM + (size_t)bx * 128) * DD;

    const uint16_t* sAhi = reinterpret_cast<const uint16_t*>(smem + OFF_AHI);
    const uint16_t* sAlo = reinterpret_cast<const uint16_t*>(smem + OFF_ALO);
    const uint16_t* sBhi = reinterpret_cast<const uint16_t*>(smem + (diag ? OFF_AHI : OFF_BHI));
    const uint16_t* sBlo = reinterpret_cast<const uint16_t*>(smem + (diag ? OFF_ALO : OFF_BLO));

    float c[2][8][4];
#pragma unroll
    for (int mi = 0; mi < 2; mi++)
#pragma unroll
        for (int ni = 0; ni < 8; ni++)
#pragma unroll
            for (int r = 0; r < 4; r++) c[mi][ni][r] = 0.f;

    float nA[4] = {0.f, 0.f, 0.f, 0.f};
    float nB[4] = {0.f, 0.f, 0.f, 0.f};

#pragma unroll 1
    for (int ch = 0; ch < 8; ch++) {
        int k0 = ch << 5;
        __syncthreads();
        load_chunk(Abase, k0, smem, OFF_AHI, OFF_ALO, tid, nA);
        if (!diag) load_chunk(Bbase, k0, smem, OFF_BHI, OFF_BLO, tid, nB);
        __syncthreads();

#pragma unroll
        for (int ks = 0; ks < 2; ks++) {
            int kk = (ks << 4) + (tg << 1);
            uint32_t ah[2][4], al[2][4];
#pragma unroll
            for (int mi = 0; mi < 2; mi++) {
                int r0 = ((wm << 5) + (mi << 4) + g) * LDA + kk;
                int r1 = r0 + (LDA << 3);
                ah[mi][0] = *reinterpret_cast<const uint32_t*>(&sAhi[r0]);
                ah[mi][1] = *reinterpret_cast<const uint32_t*>(&sAhi[r1]);
                ah[mi][2] = *reinterpret_cast<const uint32_t*>(&sAhi[r0 + 8]);
                ah[mi][3] = *reinterpret_cast<const uint32_t*>(&sAhi[r1 + 8]);
                al[mi][0] = *reinterpret_cast<const uint32_t*>(&sAlo[r0]);
                al[mi][1] = *reinterpret_cast<const uint32_t*>(&sAlo[r1]);
                al[mi][2] = *reinterpret_cast<const uint32_t*>(&sAlo[r0 + 8]);
                al[mi][3] = *reinterpret_cast<const uint32_t*>(&sAlo[r1 + 8]);
            }
            uint32_t bh[8][2], bl[8][2];
#pragma unroll
            for (int ni = 0; ni < 8; ni++) {
                int rb = ((wn << 6) + (ni << 3) + g) * LDA + kk;
                bh[ni][0] = *reinterpret_cast<const uint32_t*>(&sBhi[rb]);
                bh[ni][1] = *reinterpret_cast<const uint32_t*>(&sBhi[rb + 8]);
                bl[ni][0] = *reinterpret_cast<const uint32_t*>(&sBlo[rb]);
                bl[ni][1] = *reinterpret_cast<const uint32_t*>(&sBlo[rb + 8]);
            }
#pragma unroll
            for (int mi = 0; mi < 2; mi++)
#pragma unroll
                for (int ni = 0; ni < 8; ni++) {
                    MMA16816(c[mi][ni][0], c[mi][ni][1], c[mi][ni][2], c[mi][ni][3],
                             ah[mi][0], ah[mi][1], ah[mi][2], ah[mi][3],
                             bh[ni][0], bh[ni][1]);
                    MMA16816(c[mi][ni][0], c[mi][ni][1], c[mi][ni][2], c[mi][ni][3],
                             ah[mi][0], ah[mi][1], ah[mi][2], ah[mi][3],
                             bl[ni][0], bl[ni][1]);
                    MMA16816(c[mi][ni][0], c[mi][ni][1], c[mi][ni][2], c[mi][ni][3],
                             al[mi][0], al[mi][1], al[mi][2], al[mi][3],
                             bh[ni][0], bh[ni][1]);
                }
        }
    }

    // norms: row = tid>>3 + 32*it, owned by 8 consecutive lanes -> shfl reduce
#pragma unroll
    for (int it = 0; it < 4; it++) {
        float n = nA[it];
        n += __shfl_xor_sync(0xffffffffu, n, 1);
        n += __shfl_xor_sync(0xffffffffu, n, 2);
        n += __shfl_xor_sync(0xffffffffu, n, 4);
        if ((tid & 7) == 0) sNi[(tid >> 3) + (it << 5)] = n;
        if (!diag) {
            float m = nB[it];
            m += __shfl_xor_sync(0xffffffffu, m, 1);
            m += __shfl_xor_sync(0xffffffffu, m, 2);
            m += __shfl_xor_sync(0xffffffffu, m, 4);
            if ((tid & 7) == 0) sNj[(tid >> 3) + (it << 5)] = m;
        }
    }
    __syncthreads();   // norms visible; operand smem dead -> tables overlay it

    // distances in place of accumulators
#pragma unroll
    for (int mi = 0; mi < 2; mi++) {
        int i0 = (wm << 5) + (mi << 4) + g;
#pragma unroll
        for (int ni = 0; ni < 8; ni++) {
            int j0 = (wn << 6) + (ni << 3) + (tg << 1);
            c[mi][ni][0] = sqrtf(fmaxf(sNi[i0]     + sNj[j0]     - 2.f * c[mi][ni][0], 0.f));
            c[mi][ni][1] = sqrtf(fmaxf(sNi[i0]     + sNj[j0 + 1] - 2.f * c[mi][ni][1], 0.f));
            c[mi][ni][2] = sqrtf(fmaxf(sNi[i0 + 8] + sNj[j0]     - 2.f * c[mi][ni][2], 0.f));
            c[mi][ni][3] = sqrtf(fmaxf(sNi[i0 + 8] + sNj[j0 + 1] - 2.f * c[mi][ni][3], 0.f));
        }
    }

    float*  sSR = reinterpret_cast<float*>(smem + OFF_SR);   // stride 20
    float2* sTR = reinterpret_cast<float2*>(smem + OFF_TR);  // stride 17
    float*  sSC = reinterpret_cast<float*>(smem + OFF_SC);   // stride 20
    float2* sTC = reinterpret_cast<float2*>(smem + OFF_TC);  // stride 17

    if (diag) {
        // scatter same-class C values (classes are 16-aligned: class = idx>>4)
        float* sPos = reinterpret_cast<float*>(smem + OFF_SC);
#pragma unroll
        for (int mi = 0; mi < 2; mi++) {
            int ia = (wm << 5) + (mi << 4) + g, ib = ia + 8;
#pragma unroll
            for (int ni = 0; ni < 8; ni++) {
                int j0 = (wn << 6) + (ni << 3) + (tg << 1);
#pragma unroll
                for (int e = 0; e < 2; e++) {
                    int j = j0 + e;
                    if ((ia >> 4) == (j >> 4)) sPos[(ia << 4) + (j & 15)] = MARGIN + c[mi][ni][e];
                    if ((ib >> 4) == (j >> 4)) sPos[(ib << 4) + (j & 15)] = MARGIN + c[mi][ni][2 + e];
                }
            }
        }
        __syncthreads();
        // per-anchor rank sort + suffix sums; local tables (overwrites sPos
        // region interleaved is safe: each tid reads its own 16, writes its own 20? No:
        // sPos overlays sSC, local sort target is sSR (different region) — safe.)
        if (tid < 128) {
            float v[16];
#pragma unroll
            for (int k = 0; k < 16; k++) v[k] = sPos[(tid << 4) + k];
            float* ss = &sSR[tid * 20];
#pragma unroll
            for (int k = 0; k < 16; k++) {
                float vk = v[k];
                int r = 0;
#pragma unroll
                for (int jj = 0; jj < 16; jj++)
                    r += (int)((v[jj] < vk) | ((v[jj] == vk) & (jj < k)));
                ss[r] = vk;
            }
            size_t ab = (size_t)p * MM + by * 128 + tid;
            float run = 0.f;
            sTR[tid * 17 + 16] = make_float2(0.f, 0.f);
            g_tsuf[ab * 17 + 16] = make_float2(0.f, 0.f);
#pragma unroll
            for (int k = 15; k >= 0; k--) {
                run += ss[k];
                float2 tv = make_float2(run, (float)(16 - k));
                sTR[tid * 17 + k] = tv;
                g_tsuf[ab * 17 + k] = tv;
                g_tsort[ab * 16 + k] = ss[k];
            }
        }
        __threadfence();
        __syncthreads();
        if (tid == 0)
            asm volatile("st.release.gpu.global.b32 [%0], %1;"
                         :: "l"(&g_ready[bid]), "r"(1) : "memory");
    } else {
        // wait for both producer diag CTAs, then load tables
        if (tid == 0) {
            const int* f1 = &g_ready[(p << 2) + by];
            const int* f2 = &g_ready[(p << 2) + bx];
            int r1, r2;
            while (true) {
                asm volatile("ld.acquire.gpu.global.b32 %0, [%1];" : "=r"(r1) : "l"(f1) : "memory");
                asm volatile("ld.acquire.gpu.global.b32 %0, [%1];" : "=r"(r2) : "l"(f2) : "memory");
                if (r1 && r2) break;
                __nanosleep(128);
            }
        }
        __syncthreads();
        size_t rb16 = ((size_t)p * MM + by * 128) * 16;
        size_t rb17 = ((size_t)p * MM + by * 128) * 17;
        size_t cb16 = ((size_t)p * MM + bx * 128) * 16;
        size_t cb17 = ((size_t)p * MM + bx * 128) * 17;
        for (int q = tid; q < 2048; q += 256) {
            sSR[(q >> 4) * 20 + (q & 15)] = g_tsort[rb16 + q];
            sSC[(q >> 4) * 20 + (q & 15)] = g_tsort[cb16 + q];
        }
        for (int q = tid; q < 2176; q += 256) {
            sTR[q] = g_tsuf[rb17 + q];
            sTC[q] = g_tsuf[cb17 + q];
        }
        __syncthreads();
    }

    // hinge: row anchors hoisted (base ptr + S[7]); col S[7] hoisted per column
    const int abase = wm << 5;
    int aIdx[4] = {abase + g, abase + g + 8, abase + 16 + g, abase + 24 + g};
    const float*  SR[4]; const float2* TR[4];
    float S7[4];
#pragma unroll
    for (int q = 0; q < 4; q++) {
        SR[q] = &sSR[aIdx[q] * 20];
        TR[q] = &sTR[aIdx[q] * 17];
        S7[q] = SR[q][7];
    }
    float aA = 0.f, aB = 0.f, aC = 0.f;
#pragma unroll
    for (int ni = 0; ni < 8; ni++) {
#pragma unroll
        for (int e = 0; e < 2; e++) {
            int j = (wn << 6) + (ni << 3) + (tg << 1) + e;
            const float* SCj = &sSC[j * 20];
            const float2* TCj = &sTC[j * 17];
            float c7 = 0.f;
            if (!diag) c7 = SCj[7];
            int jc = j >> 4;
#pragma unroll
            for (int mi = 0; mi < 2; mi++) {
                float d0 = c[mi][ni][e];
                float d1 = c[mi][ni][2 + e];
                const int q0 = mi << 1, q1 = q0 + 1;
                bool ok0 = !diag || ((aIdx[q0] >> 4) != jc);
                bool ok1 = !diag || ((aIdx[q1] >> 4) != jc);
                if (ok0) searchv(SR[q0], TR[q0], S7[q0], d0, aA, aB, aC);
                if (ok1) searchv(SR[q1], TR[q1], S7[q1], d1, aA, aB, aC);
                if (!diag) {
                    searchv(SCj, TCj, c7, d0, aA, aB, aC);
                    searchv(SCj, TCj, c7, d1, aA, aB, aC);
                }
            }
        }
    }

    float loss = aA - aB, cnt = aC;
#pragma unroll
    for (int o = 16; o; o >>= 1) {
        loss += __shfl_xor_sync(0xffffffffu, loss, o);
        cnt  += __shfl_xor_sync(0xffffffffu, cnt, o);
    }
    float* sRed = reinterpret_cast<float*>(smem + OFF_RED);
    if (lane == 0) { sRed[w] = loss; sRed[8 + w] = cnt; }
    __syncthreads();
    if (tid == 0) {
        float L = 0.f, C = 0.f;
#pragma unroll
        for (int k = 0; k < 8; k++) { L += sRed[k]; C += sRed[8 + k]; }
        atomicAdd(&g_psum[p], L);
        atomicAdd(&g_pcnt[p], C);
    }
}

// ---------------------------------------------------------------------------
// final reduce + reset state for the next (graph-replayed) launch
// ---------------------------------------------------------------------------
__global__ void final_kernel(float* __restrict__ out, int out_size) {
    __shared__ float sa[2], sb2[2];
    int t = threadIdx.x;          // 64 threads
    float cnt = g_pcnt[t], sum = g_psum[t];
    float a = (cnt > 0.f) ? sum / fmaxf(cnt, 1.f) : 0.f;
    float b = cnt;
#pragma unroll
    for (int o = 16; o; o >>= 1) {
        a += __shfl_xor_sync(0xffffffffu, a, o);
        b += __shfl_xor_sync(0xffffffffu, b, o);
    }
    if ((t & 31) == 0) { sa[t >> 5] = a; sb2[t >> 5] = b; }
    __syncthreads();
    if (t == 0) {
        out[0] = (sa[0] + sa[1]) / (float)NP;
        if (out_size > 1) out[1] = (sb2[0] + sb2[1]) / (float)NP;
    }
    // reset state (reads above are done: same-address dependence per thread,
    // cross-thread reads fenced by the __syncthreads)
    g_psum[t] = 0.f;
    g_pcnt[t] = 0.f;
#pragma unroll
    for (int q = 0; q < 4; q++) g_ready[t + (q << 6)] = 0;
}

extern "C" void kernel_launch(void* const* d_in, const int* in_sizes, int n_in,
                              void* d_out, int out_size) {
    const float* feat = (const float*)d_in[0];
    (void)in_sizes; (void)n_in;

    cudaFuncSetAttribute(fused_kernel, cudaFuncAttributeMaxDynamicSharedMemorySize, SMEM_TOTAL);

    fused_kernel<<<640, 256, SMEM_TOTAL>>>(feat);
    final_kernel<<<1, 64>>>((float*)d_out, out_size);
}

// round 11
// speedup vs baseline: 1.0508x; 1.0508x over previous
#include <cuda_runtime.h>
#include <cuda_bf16.h>
#include <cstdint>
#include <math.h>

#define NP 64
#define MM 512
#define DD 256
#define MARGIN 0.2f

__device__ float  g_psum[NP];
__device__ float  g_pcnt[NP];
__device__ float  g_tsort[(size_t)NP * MM * 16];   // per-anchor sorted C values
__device__ float2 g_tsuf [(size_t)NP * MM * 17];   // per-anchor (suffix sum, count)
__device__ int    g_ready[NP * 4];                 // per (part, diag block) flag
// all zero-initialized at module load; final_kernel re-zeros after each launch

// off-diagonal tile map (6 tiles of the 4x4 upper triangle)
__constant__ int c_oby[6] = {0,0,0,1,1,2};
__constant__ int c_obx[6] = {1,2,3,2,3,3};

// ---------------------------------------------------------------------------
__device__ __forceinline__ void split2(float x0, float x1, uint32_t& hi, uint32_t& lo) {
    uint32_t h;
    asm("cvt.rn.bf16x2.f32 %0, %1, %2;" : "=r"(h) : "f"(x1), "f"(x0));
    float h0 = __uint_as_float(h << 16);
    float h1 = __uint_as_float(h & 0xFFFF0000u);
    float r0 = x0 - h0, r1 = x1 - h1;
    asm("cvt.rn.bf16x2.f32 %0, %1, %2;" : "=r"(lo) : "f"(r1), "f"(r0));
    hi = h;
}

#define MMA16816(c0,c1,c2,c3, a0,a1,a2,a3, b0,b1) \
    asm volatile("mma.sync.aligned.m16n8k16.row.col.f32.bf16.bf16.f32 " \
                 "{%0,%1,%2,%3}, {%4,%5,%6,%7}, {%8,%9}, {%0,%1,%2,%3};" \
                 : "+f"(c0), "+f"(c1), "+f"(c2), "+f"(c3) \
                 : "r"(a0), "r"(a1), "r"(a2), "r"(a3), "r"(b0), "r"(b1))

// SMEM layout. Mainloop operands [0, 40960); epilogue tables overlay after a
// barrier (all table writes happen post-mainloop). Norms/reduce live above.
#define LDA 40
#define TILE_B (128 * LDA * 2)        // 10240
#define OFF_AHI 0
#define OFF_ALO (TILE_B)
#define OFF_BHI (2 * TILE_B)
#define OFF_BLO (3 * TILE_B)          // operands end at 40960
#define OFF_SR  0                     // float [128*17]
#define OFF_TR  8704                  // float2[128*17]
#define OFF_SC  26112                 // float [128*17] (diag: sPos 128*16)
#define OFF_TC  34816                 // float2[128*17] -> 52224
#define OFF_NRM 52224                 // 256 floats
#define OFF_RED 53248                 // 16 floats
#define SMEM_TOTAL 53440

__device__ __forceinline__ void load_chunk(
    const float* __restrict__ src, int k0, char* smem, int off_hi, int off_lo,
    int tid, float* __restrict__ nacc)
{
    uint16_t* shi = reinterpret_cast<uint16_t*>(smem + off_hi);
    uint16_t* slo = reinterpret_cast<uint16_t*>(smem + off_lo);
#pragma unroll
    for (int it = 0; it < 4; it++) {
        int q   = tid + (it << 8);
        int row = q >> 3;
        int c4  = q & 7;
        float4 v = *reinterpret_cast<const float4*>(src + (size_t)row * DD + k0 + (c4 << 2));
        nacc[it] = fmaf(v.x, v.x, nacc[it]);
        nacc[it] = fmaf(v.y, v.y, nacc[it]);
        nacc[it] = fmaf(v.z, v.z, nacc[it]);
        nacc[it] = fmaf(v.w, v.w, nacc[it]);
        uint32_t h0, h1, l0, l1;
        split2(v.x, v.y, h0, l0);
        split2(v.z, v.w, h1, l1);
        int idx = row * LDA + (c4 << 2);
        *reinterpret_cast<uint2*>(&shi[idx]) = make_uint2(h0, h1);
        *reinterpret_cast<uint2*>(&slo[idx]) = make_uint2(l0, l1);
    }
}

// 4-step scalar binary search with hoisted S[7]/S[15]; idx in [0,16]
__device__ __forceinline__ void search2(
    const float* __restrict__ S, const float2* __restrict__ T,
    float s7, float s15, float d, float& aA, float& aB, float& aC)
{
    int idx = (s7 <= d) ? 8 : 0;
    idx += (S[idx + 3] <= d) ? 4 : 0;
    idx += (S[idx + 1] <= d) ? 2 : 0;
    idx += (S[idx]     <= d) ? 1 : 0;
    idx = (s15 <= d) ? 16 : idx;
    float2 t = T[idx];
    aA += t.x;
    aB  = fmaf(t.y, d, aB);
    aC += t.y;
}

// ---------------------------------------------------------------------------
// fused GEMM + norms + table build (diag) + hinge. 1-D grid of 640:
//   bid < 256  -> diag:    p = bid>>2, by = bx = bid&3 (flag index = bid)
//   bid >= 256 -> offdiag: q = bid-256, p = q/6, tile = q%6
// ---------------------------------------------------------------------------
__global__ void __launch_bounds__(256, 2) fused_kernel(const float* __restrict__ feat) {
    extern __shared__ char smem[];
    const int tid = threadIdx.x;
    const int w = tid >> 5, lane = tid & 31;
    const int g = lane >> 2, tg = lane & 3;
    const int wm = w >> 1, wn = w & 1;
    const int bid = blockIdx.x;
    const bool diag = (bid < 256);
    int p, by, bx;
    if (diag) {
        p = bid >> 2; by = bx = bid & 3;
    } else {
        int q = bid - 256;
        p = q / 6;
        int t = q - p * 6;
        by = c_oby[t]; bx = c_obx[t];
    }

    float* sNi = reinterpret_cast<float*>(smem + OFF_NRM);
    float* sNj = diag ? sNi : (sNi + 128);

    const float* Abase = feat + ((size_t)p * MM + (size_t)by * 128) * DD;
    const float* Bbase = feat + ((size_t)p * MM + (size_t)bx * 128) * DD;

    const uint16_t* sAhi = reinterpret_cast<const uint16_t*>(smem + OFF_AHI);
    const uint16_t* sAlo = reinterpret_cast<const uint16_t*>(smem + OFF_ALO);
    const uint16_t* sBhi = reinterpret_cast<const uint16_t*>(smem + (diag ? OFF_AHI : OFF_BHI));
    const uint16_t* sBlo = reinterpret_cast<const uint16_t*>(smem + (diag ? OFF_ALO : OFF_BLO));

    float c[2][8][4];
#pragma unroll
    for (int mi = 0; mi < 2; mi++)
#pragma unroll
        for (int ni = 0; ni < 8; ni++)
#pragma unroll
            for (int r = 0; r < 4; r++) c[mi][ni][r] = 0.f;

    float nA[4] = {0.f, 0.f, 0.f, 0.f};
    float nB[4] = {0.f, 0.f, 0.f, 0.f};

#pragma unroll 1
    for (int ch = 0; ch < 8; ch++) {
        int k0 = ch << 5;
        __syncthreads();
        load_chunk(Abase, k0, smem, OFF_AHI, OFF_ALO, tid, nA);
        if (!diag) load_chunk(Bbase, k0, smem, OFF_BHI, OFF_BLO, tid, nB);
        __syncthreads();

#pragma unroll
        for (int ks = 0; ks < 2; ks++) {
            int kk = (ks << 4) + (tg << 1);
            uint32_t ah[2][4], al[2][4];
#pragma unroll
            for (int mi = 0; mi < 2; mi++) {
                int r0 = ((wm << 5) + (mi << 4) + g) * LDA + kk;
                int r1 = r0 + (LDA << 3);
                ah[mi][0] = *reinterpret_cast<const uint32_t*>(&sAhi[r0]);
                ah[mi][1] = *reinterpret_cast<const uint32_t*>(&sAhi[r1]);
                ah[mi][2] = *reinterpret_cast<const uint32_t*>(&sAhi[r0 + 8]);
                ah[mi][3] = *reinterpret_cast<const uint32_t*>(&sAhi[r1 + 8]);
                al[mi][0] = *reinterpret_cast<const uint32_t*>(&sAlo[r0]);
                al[mi][1] = *reinterpret_cast<const uint32_t*>(&sAlo[r1]);
                al[mi][2] = *reinterpret_cast<const uint32_t*>(&sAlo[r0 + 8]);
                al[mi][3] = *reinterpret_cast<const uint32_t*>(&sAlo[r1 + 8]);
            }
            uint32_t bh[8][2], bl[8][2];
#pragma unroll
            for (int ni = 0; ni < 8; ni++) {
                int rb = ((wn << 6) + (ni << 3) + g) * LDA + kk;
                bh[ni][0] = *reinterpret_cast<const uint32_t*>(&sBhi[rb]);
                bh[ni][1] = *reinterpret_cast<const uint32_t*>(&sBhi[rb + 8]);
                bl[ni][0] = *reinterpret_cast<const uint32_t*>(&sBlo[rb]);
                bl[ni][1] = *reinterpret_cast<const uint32_t*>(&sBlo[rb + 8]);
            }
#pragma unroll
            for (int mi = 0; mi < 2; mi++)
#pragma unroll
                for (int ni = 0; ni < 8; ni++) {
                    MMA16816(c[mi][ni][0], c[mi][ni][1], c[mi][ni][2], c[mi][ni][3],
                             ah[mi][0], ah[mi][1], ah[mi][2], ah[mi][3],
                             bh[ni][0], bh[ni][1]);
                    MMA16816(c[mi][ni][0], c[mi][ni][1], c[mi][ni][2], c[mi][ni][3],
                             ah[mi][0], ah[mi][1], ah[mi][2], ah[mi][3],
                             bl[ni][0], bl[ni][1]);
                    MMA16816(c[mi][ni][0], c[mi][ni][1], c[mi][ni][2], c[mi][ni][3],
                             al[mi][0], al[mi][1], al[mi][2], al[mi][3],
                             bh[ni][0], bh[ni][1]);
                }
        }
    }

    // norms: row = tid>>3 + 32*it, owned by 8 consecutive lanes -> shfl reduce
#pragma unroll
    for (int it = 0; it < 4; it++) {
        float n = nA[it];
        n += __shfl_xor_sync(0xffffffffu, n, 1);
        n += __shfl_xor_sync(0xffffffffu, n, 2);
        n += __shfl_xor_sync(0xffffffffu, n, 4);
        if ((tid & 7) == 0) sNi[(tid >> 3) + (it << 5)] = n;
        if (!diag) {
            float m = nB[it];
            m += __shfl_xor_sync(0xffffffffu, m, 1);
            m += __shfl_xor_sync(0xffffffffu, m, 2);
            m += __shfl_xor_sync(0xffffffffu, m, 4);
            if ((tid & 7) == 0) sNj[(tid >> 3) + (it << 5)] = m;
        }
    }
    __syncthreads();   // norms visible; operand smem dead -> tables overlay it

    // distances in place of accumulators
#pragma unroll
    for (int mi = 0; mi < 2; mi++) {
        int i0 = (wm << 5) + (mi << 4) + g;
#pragma unroll
        for (int ni = 0; ni < 8; ni++) {
            int j0 = (wn << 6) + (ni << 3) + (tg << 1);
            c[mi][ni][0] = sqrtf(fmaxf(sNi[i0]     + sNj[j0]     - 2.f * c[mi][ni][0], 0.f));
            c[mi][ni][1] = sqrtf(fmaxf(sNi[i0]     + sNj[j0 + 1] - 2.f * c[mi][ni][1], 0.f));
            c[mi][ni][2] = sqrtf(fmaxf(sNi[i0 + 8] + sNj[j0]     - 2.f * c[mi][ni][2], 0.f));
            c[mi][ni][3] = sqrtf(fmaxf(sNi[i0 + 8] + sNj[j0 + 1] - 2.f * c[mi][ni][3], 0.f));
        }
    }

    float*  sSR = reinterpret_cast<float*>(smem + OFF_SR);   // stride 17
    float2* sTR = reinterpret_cast<float2*>(smem + OFF_TR);  // stride 17
    float*  sSC = reinterpret_cast<float*>(smem + OFF_SC);   // stride 17
    float2* sTC = reinterpret_cast<float2*>(smem + OFF_TC);  // stride 17

    if (diag) {
        // scatter same-class C values (classes are 16-aligned: class = idx>>4)
        float* sPos = reinterpret_cast<float*>(smem + OFF_SC);
#pragma unroll
        for (int mi = 0; mi < 2; mi++) {
            int ia = (wm << 5) + (mi << 4) + g, ib = ia + 8;
#pragma unroll
            for (int ni = 0; ni < 8; ni++) {
                int j0 = (wn << 6) + (ni << 3) + (tg << 1);
#pragma unroll
                for (int e = 0; e < 2; e++) {
                    int j = j0 + e;
                    if ((ia >> 4) == (j >> 4)) sPos[(ia << 4) + (j & 15)] = MARGIN + c[mi][ni][e];
                    if ((ib >> 4) == (j >> 4)) sPos[(ib << 4) + (j & 15)] = MARGIN + c[mi][ni][2 + e];
                }
            }
        }
        __syncthreads();
        // per-anchor rank sort + suffix sums; local tables + publish
        if (tid < 128) {
            float v[16];
#pragma unroll
            for (int k = 0; k < 16; k++) v[k] = sPos[(tid << 4) + k];
            float* ss = &sSR[tid * 17];
#pragma unroll
            for (int k = 0; k < 16; k++) {
                float vk = v[k];
                int r = 0;
#pragma unroll
                for (int jj = 0; jj < 16; jj++)
                    r += (int)((v[jj] < vk) | ((v[jj] == vk) & (jj < k)));
                ss[r] = vk;
            }
            size_t ab = (size_t)p * MM + by * 128 + tid;
            float run = 0.f;
            sTR[tid * 17 + 16] = make_float2(0.f, 0.f);
            g_tsuf[ab * 17 + 16] = make_float2(0.f, 0.f);
#pragma unroll
            for (int k = 15; k >= 0; k--) {
                run += ss[k];
                float2 tv = make_float2(run, (float)(16 - k));
                sTR[tid * 17 + k] = tv;
                g_tsuf[ab * 17 + k] = tv;
                g_tsort[ab * 16 + k] = ss[k];
            }
        }
        __threadfence();
        __syncthreads();
        if (tid == 0)
            asm volatile("st.release.gpu.global.b32 [%0], %1;"
                         :: "l"(&g_ready[bid]), "r"(1) : "memory");
    } else {
        // wait for both producer diag CTAs, then load tables
        if (tid == 0) {
            const int* f1 = &g_ready[(p << 2) + by];
            const int* f2 = &g_ready[(p << 2) + bx];
            int r1, r2;
            while (true) {
                asm volatile("ld.acquire.gpu.global.b32 %0, [%1];" : "=r"(r1) : "l"(f1) : "memory");
                asm volatile("ld.acquire.gpu.global.b32 %0, [%1];" : "=r"(r2) : "l"(f2) : "memory");
                if (r1 && r2) break;
                __nanosleep(128);
            }
        }
        __syncthreads();
        size_t rb16 = ((size_t)p * MM + by * 128) * 16;
        size_t rb17 = ((size_t)p * MM + by * 128) * 17;
        size_t cb16 = ((size_t)p * MM + bx * 128) * 16;
        size_t cb17 = ((size_t)p * MM + bx * 128) * 17;
        for (int q = tid; q < 2048; q += 256) {
            sSR[(q >> 4) * 17 + (q & 15)] = g_tsort[rb16 + q];
            sSC[(q >> 4) * 17 + (q & 15)] = g_tsort[cb16 + q];
        }
        for (int q = tid; q < 2176; q += 256) {
            sTR[q] = g_tsuf[rb17 + q];
            sTC[q] = g_tsuf[cb17 + q];
        }
        __syncthreads();
    }

    // hinge searches: row anchors hoisted; col S7/S15 hoisted per column
    const int abase = wm << 5;
    int aIdx[4] = {abase + g, abase + g + 8, abase + 16 + g, abase + 24 + g};
    const float*  SR[4]; const float2* TR[4];
    float S7[4], S15[4];
#pragma unroll
    for (int q = 0; q < 4; q++) {
        SR[q]  = &sSR[aIdx[q] * 17];
        TR[q]  = &sTR[aIdx[q] * 17];
        S7[q]  = SR[q][7];
        S15[q] = SR[q][15];
    }
    float aA = 0.f, aB = 0.f, aC = 0.f;
#pragma unroll
    for (int ni = 0; ni < 8; ni++) {
#pragma unroll
        for (int e = 0; e < 2; e++) {
            int j = (wn << 6) + (ni << 3) + (tg << 1) + e;
            float c7 = 0.f, c15 = 0.f;
            const float* SCj = &sSC[j * 17];
            const float2* TCj = &sTC[j * 17];
            if (!diag) { c7 = SCj[7]; c15 = SCj[15]; }
            int jc = j >> 4;
#pragma unroll
            for (int mi = 0; mi < 2; mi++) {
                float d0 = c[mi][ni][e];
                float d1 = c[mi][ni][2 + e];
                const int q0 = mi << 1, q1 = q0 + 1;
                bool ok0 = !diag || ((aIdx[q0] >> 4) != jc);
                bool ok1 = !diag || ((aIdx[q1] >> 4) != jc);
                if (ok0) search2(SR[q0], TR[q0], S7[q0], S15[q0], d0, aA, aB, aC);
                if (ok1) search2(SR[q1], TR[q1], S7[q1], S15[q1], d1, aA, aB, aC);
                if (!diag) {
                    search2(SCj, TCj, c7, c15, d0, aA, aB, aC);
                    search2(SCj, TCj, c7, c15, d1, aA, aB, aC);
                }
            }
        }
    }

    float loss = aA - aB, cnt = aC;
#pragma unroll
    for (int o = 16; o; o >>= 1) {
        loss += __shfl_xor_sync(0xffffffffu, loss, o);
        cnt  += __shfl_xor_sync(0xffffffffu, cnt, o);
    }
    float* sRed = reinterpret_cast<float*>(smem + OFF_RED);
    if (lane == 0) { sRed[w] = loss; sRed[8 + w] = cnt; }
    __syncthreads();
    if (tid == 0) {
        float L = 0.f, C = 0.f;
#pragma unroll
        for (int k = 0; k < 8; k++) { L += sRed[k]; C += sRed[8 + k]; }
        atomicAdd(&g_psum[p], L);
        atomicAdd(&g_pcnt[p], C);
    }
}

// ---------------------------------------------------------------------------
// final reduce + reset state for the next (graph-replayed) launch
// ---------------------------------------------------------------------------
__global__ void final_kernel(float* __restrict__ out, int out_size) {
    __shared__ float sa[2], sb2[2];
    int t = threadIdx.x;          // 64 threads
    float cnt = g_pcnt[t], sum = g_psum[t];
    float a = (cnt > 0.f) ? sum / fmaxf(cnt, 1.f) : 0.f;
    float b = cnt;
#pragma unroll
    for (int o = 16; o; o >>= 1) {
        a += __shfl_xor_sync(0xffffffffu, a, o);
        b += __shfl_xor_sync(0xffffffffu, b, o);
    }
    if ((t & 31) == 0) { sa[t >> 5] = a; sb2[t >> 5] = b; }
    __syncthreads();
    if (t == 0) {
        out[0] = (sa[0] + sa[1]) / (float)NP;
        if (out_size > 1) out[1] = (sb2[0] + sb2[1]) / (float)NP;
    }
    // reset state for the next launch (reads above complete before these)
    g_psum[t] = 0.f;
    g_pcnt[t] = 0.f;
#pragma unroll
    for (int q = 0; q < 4; q++) g_ready[t + (q << 6)] = 0;
}

extern "C" void kernel_launch(void* const* d_in, const int* in_sizes, int n_in,
                              void* d_out, int out_size) {
    const float* feat = (const float*)d_in[0];
    (void)in_sizes; (void)n_in;

    cudaFuncSetAttribute(fused_kernel, cudaFuncAttributeMaxDynamicSharedMemorySize, SMEM_TOTAL);

    fused_kernel<<<640, 256, SMEM_TOTAL>>>(feat);
    final_kernel<<<1, 64>>>((float*)d_out, out_size);
}